// round 1
// baseline (speedup 1.0000x reference)
#include <cuda_runtime.h>
#include <cuda_bf16.h>
#include <math.h>

// Scratch for per-patch correlation values (no dynamic allocation allowed).
__device__ float g_co[1 << 16];

#define FULLMASK 0xFFFFFFFFu

// One warp per patch. lane = column within the 32-wide box; loop over 32 rows.
// Each row load is a fully-coalesced 128B segment (misaligned by y0, which the
// L1/L2 sectors absorb). Five moments accumulated per-lane, then a 5-way
// warp-shuffle tree reduction; lane 0 computes the Pearson coefficient.
template <int BOX>
__global__ __launch_bounds__(256)
void patch_corr_kernel(const float* __restrict__ pred,
                       const float* __restrict__ gt,
                       const int* __restrict__ x0,
                       const int* __restrict__ y0,
                       int n_corr, int W)
{
    const int warp = (int)((blockIdx.x * blockDim.x + threadIdx.x) >> 5);
    const int lane = (int)(threadIdx.x & 31);
    if (warp >= n_corr) return;

    const int bx = x0[warp];
    const int by = y0[warp];
    const size_t base = (size_t)bx * (size_t)W + (size_t)by + (size_t)lane;
    const float* __restrict__ p0 = pred + base;
    const float* __restrict__ g0 = gt + base;

    float sp = 0.f, sg = 0.f, spp = 0.f, sgg = 0.f, spg = 0.f;

#pragma unroll
    for (int r = 0; r < BOX; ++r) {
        const float p = p0[(size_t)r * (size_t)W];
        const float g = g0[(size_t)r * (size_t)W];
        sp += p;
        sg += g;
        spp = fmaf(p, p, spp);
        sgg = fmaf(g, g, sgg);
        spg = fmaf(p, g, spg);
    }

    // Warp tree reduction of the five moments.
#pragma unroll
    for (int o = 16; o > 0; o >>= 1) {
        sp  += __shfl_xor_sync(FULLMASK, sp,  o);
        sg  += __shfl_xor_sync(FULLMASK, sg,  o);
        spp += __shfl_xor_sync(FULLMASK, spp, o);
        sgg += __shfl_xor_sync(FULLMASK, sgg, o);
        spg += __shfl_xor_sync(FULLMASK, spg, o);
    }

    if (lane == 0) {
        const float P = (float)(BOX * BOX);
        const float EPS = 1e-6f;
        // co = mean((p-mp)(g-mg)) / ((std_p+eps)*(std_g+eps)), std unbiased.
        const float cov_sum = spg - sp * sg * (1.f / P);
        const float vp_sum  = spp - sp * sp * (1.f / P);
        const float vg_sum  = sgg - sg * sg * (1.f / P);
        const float inv_pm1 = 1.f / (P - 1.f);
        const float sdp = sqrtf(fmaxf(vp_sum, 0.f) * inv_pm1);
        const float sdg = sqrtf(fmaxf(vg_sum, 0.f) * inv_pm1);
        const float co = (cov_sum * (1.f / P)) / ((sdp + EPS) * (sdg + EPS));
        g_co[warp] = co;
    }
}

// Single-block final reduction: loss = sum(1 - co) / n = (n - sum(co)) / n.
// Double accumulators: trivially cheap for 8192 elements, removes any
// accumulation-order worry for the 1e-3 rel-err gate.
__global__ __launch_bounds__(1024)
void loss_reduce_kernel(float* __restrict__ out, int n)
{
    __shared__ double sh[32];
    double acc = 0.0;
    for (int i = (int)threadIdx.x; i < n; i += (int)blockDim.x)
        acc += (double)g_co[i];

#pragma unroll
    for (int o = 16; o > 0; o >>= 1)
        acc += __shfl_xor_sync(FULLMASK, acc, o);

    const int lane = (int)(threadIdx.x & 31);
    const int wid  = (int)(threadIdx.x >> 5);
    if (lane == 0) sh[wid] = acc;
    __syncthreads();

    if (wid == 0) {
        const int nwarps = (int)(blockDim.x >> 5);
        acc = (lane < nwarps) ? sh[lane] : 0.0;
#pragma unroll
        for (int o = 16; o > 0; o >>= 1)
            acc += __shfl_xor_sync(FULLMASK, acc, o);
        if (lane == 0)
            out[0] = (float)(((double)n - acc) / (double)n);
    }
}

extern "C" void kernel_launch(void* const* d_in, const int* in_sizes, int n_in,
                              void* d_out, int out_size)
{
    const float* pred = (const float*)d_in[0];
    const float* gt   = (const float*)d_in[1];
    const int*   x0   = (const int*)d_in[2];
    const int*   y0   = (const int*)d_in[3];
    // d_in[4] is box_p (=32); the box size is baked into the template below.

    const int n_corr = in_sizes[2];
    // Image is C=1 x H x W with H == W; recover W from the element count.
    int W = 1;
    {
        long long elems = (long long)in_sizes[0];
        long long lo = 1, hi = 1 << 17;
        while (lo < hi) {
            long long mid = (lo + hi) >> 1;
            if (mid * mid < elems) lo = mid + 1; else hi = mid;
        }
        W = (int)lo;
    }

    constexpr int BOX = 32;
    const int warps_per_block = 256 / 32;
    const int grid = (n_corr + warps_per_block - 1) / warps_per_block;

    patch_corr_kernel<BOX><<<grid, 256>>>(pred, gt, x0, y0, n_corr, W);
    loss_reduce_kernel<<<1, 1024>>>((float*)d_out, n_corr);
}

// round 2
// speedup vs baseline: 1.0300x; 1.0300x over previous
#include <cuda_runtime.h>
#include <cuda_bf16.h>
#include <math.h>

#define FULLMASK 0xFFFFFFFFu

// Fixed-point global accumulator (Q32.32) + completion ticket counter.
// Integer atomics are associative -> bit-deterministic across replays.
// Zero-initialized at module load; the last block resets them after use so
// every graph replay starts from a clean state.
__device__ unsigned long long g_acc  = 0ULL;
__device__ unsigned int       g_done = 0u;

// One warp per patch: lane = column within the 32-wide box, loop over 32 rows.
// Each row is one coalesced 128B segment per image (misaligned by y0; the
// 32B-sector hierarchy absorbs that identically to any aligned scheme).
// Five moments -> warp shuffle reduce -> Pearson on lane 0 -> Q32.32 fixed
// point -> exact per-block integer sum -> one 64-bit atomicAdd per block.
// Last block to finish computes loss = (n - sum(co)) / n and writes d_out.
template <int BOX, int WPB>
__global__ __launch_bounds__(WPB * 32)
void fused_pearson_kernel(const float* __restrict__ pred,
                          const float* __restrict__ gt,
                          const int* __restrict__ x0,
                          const int* __restrict__ y0,
                          int n_corr, int W,
                          float* __restrict__ out)
{
    __shared__ long long sh_ll[WPB];

    const int wid  = (int)(threadIdx.x >> 5);
    const int lane = (int)(threadIdx.x & 31);
    const int warp = (int)(blockIdx.x * WPB + wid);

    long long fx = 0LL;

    if (warp < n_corr) {
        const int bx = x0[warp];
        const int by = y0[warp];
        const size_t base = (size_t)bx * (size_t)W + (size_t)by + (size_t)lane;
        const float* __restrict__ p0 = pred + base;
        const float* __restrict__ g0 = gt + base;

        float sp = 0.f, sg = 0.f, spp = 0.f, sgg = 0.f, spg = 0.f;

#pragma unroll
        for (int r = 0; r < BOX; ++r) {
            const float p = p0[(size_t)r * (size_t)W];
            const float g = g0[(size_t)r * (size_t)W];
            sp += p;
            sg += g;
            spp = fmaf(p, p, spp);
            sgg = fmaf(g, g, sgg);
            spg = fmaf(p, g, spg);
        }

#pragma unroll
        for (int o = 16; o > 0; o >>= 1) {
            sp  += __shfl_xor_sync(FULLMASK, sp,  o);
            sg  += __shfl_xor_sync(FULLMASK, sg,  o);
            spp += __shfl_xor_sync(FULLMASK, spp, o);
            sgg += __shfl_xor_sync(FULLMASK, sgg, o);
            spg += __shfl_xor_sync(FULLMASK, spg, o);
        }

        if (lane == 0) {
            const float P = (float)(BOX * BOX);
            const float EPS = 1e-6f;
            const float cov_sum = spg - sp * sg * (1.f / P);
            const float vp_sum  = spp - sp * sp * (1.f / P);
            const float vg_sum  = sgg - sg * sg * (1.f / P);
            const float inv_pm1 = 1.f / (P - 1.f);
            const float sdp = sqrtf(fmaxf(vp_sum, 0.f) * inv_pm1);
            const float sdg = sqrtf(fmaxf(vg_sum, 0.f) * inv_pm1);
            const float co  = (cov_sum * (1.f / P)) / ((sdp + EPS) * (sdg + EPS));
            // Q32.32 fixed point; double conversion is exact for this range.
            fx = llrint((double)co * 4294967296.0);
        }
    }

    if (lane == 0) sh_ll[wid] = fx;
    __syncthreads();

    if (threadIdx.x == 0) {
        long long bsum = 0LL;
#pragma unroll
        for (int i = 0; i < WPB; ++i) bsum += sh_ll[i];
        atomicAdd(&g_acc, (unsigned long long)bsum);
        __threadfence();
        const unsigned int ticket = atomicAdd(&g_done, 1u);
        if (ticket == (unsigned int)gridDim.x - 1u) {
            // Atomic read-modify-write of 0 gives a coherent view of g_acc.
            const unsigned long long tot_u = atomicAdd(&g_acc, 0ULL);
            const double sum_co = (double)(long long)tot_u * (1.0 / 4294967296.0);
            out[0] = (float)(((double)n_corr - sum_co) / (double)n_corr);
            // Reset for the next (graph-replayed) launch.
            g_acc  = 0ULL;
            g_done = 0u;
        }
    }
}

extern "C" void kernel_launch(void* const* d_in, const int* in_sizes, int n_in,
                              void* d_out, int out_size)
{
    const float* pred = (const float*)d_in[0];
    const float* gt   = (const float*)d_in[1];
    const int*   x0   = (const int*)d_in[2];
    const int*   y0   = (const int*)d_in[3];
    // d_in[4] is box_p (=32); baked into the template.

    const int n_corr = in_sizes[2];

    // Image is C=1 x H x W with H == W; recover W from the element count.
    int W = 1;
    {
        long long elems = (long long)in_sizes[0];
        long long lo = 1, hi = 1 << 17;
        while (lo < hi) {
            long long mid = (lo + hi) >> 1;
            if (mid * mid < elems) lo = mid + 1; else hi = mid;
        }
        W = (int)lo;
    }

    constexpr int BOX = 32;
    constexpr int WPB = 8;                       // 256 threads/block
    const int grid = (n_corr + WPB - 1) / WPB;

    fused_pearson_kernel<BOX, WPB><<<grid, WPB * 32>>>(
        pred, gt, x0, y0, n_corr, W, (float*)d_out);
}